// round 15
// baseline (speedup 1.0000x reference)
#include <cuda_runtime.h>
#include <cuda_bf16.h>
#include <cstdint>

// ---------------------------------------------------------------- constants
#define BB 16
#define CC_ 256
#define HWN 4096
#define EPSV 1e-5f
#define TOTAL (BB*CC_*HWN)   // 16,777,216

// ---------------------------------------------------------------- scratch
__device__ __nv_bfloat16 g_xnT_hi[TOTAL];      // [b][n][c]
__device__ __nv_bfloat16 g_xnT_lo[TOTAL];
__device__ __nv_bfloat16 g_xnC_hi[TOTAL];      // [b][c][n]
__device__ __nv_bfloat16 g_xnC_lo[TOTAL];
__device__ __nv_bfloat16 g_wqkv_hi[768*256];
__device__ __nv_bfloat16 g_wqkv_lo[768*256];
__device__ __nv_bfloat16 g_wvT_hi[256*256];    // WvT[c][c'] = Wv[c'][c]
__device__ __nv_bfloat16 g_wvT_lo[256*256];
__device__ float g_Spart[128*256*256];         // [b*8+seg][c1][c2]
__device__ __nv_bfloat16 g_S_hi[BB*256*256];
__device__ __nv_bfloat16 g_S_lo[BB*256*256];
__device__ float g_T[BB*256*256];              // T = Wq * S
__device__ float g_s1[BB*256];                 // per-channel sums of xn
__device__ float g_P[BB*64*16];
__device__ __nv_bfloat16 g_wt_hi[BB*256*256];  // W~ (P-folded proj)
__device__ __nv_bfloat16 g_wt_lo[BB*256*256];
__device__ __nv_bfloat16 g_weff_hi[BB*256*256];
__device__ __nv_bfloat16 g_weff_lo[BB*256*256];
__device__ float g_beff[BB*256];
__device__ float g_mean[BB*8];
__device__ float g_rstd[BB*8];

// ---------------------------------------------------------------- PTX helpers
__device__ __forceinline__ uint32_t smem_u32(const void* p) {
    uint32_t a;
    asm("{ .reg .u64 t; cvta.to.shared.u64 t, %1; cvt.u32.u64 %0, t; }" : "=r"(a) : "l"(p));
    return a;
}
__device__ __forceinline__ void ldsm4(uint32_t* r, uint32_t addr) {
    asm volatile("ldmatrix.sync.aligned.m8n8.x4.shared.b16 {%0,%1,%2,%3}, [%4];"
                 : "=r"(r[0]), "=r"(r[1]), "=r"(r[2]), "=r"(r[3]) : "r"(addr));
}
__device__ __forceinline__ void mma16816(float* d, const uint32_t* a, const uint32_t* b) {
    asm volatile("mma.sync.aligned.m16n8k16.row.col.f32.bf16.bf16.f32 "
                 "{%0,%1,%2,%3}, {%4,%5,%6,%7}, {%8,%9}, {%0,%1,%2,%3};"
                 : "+f"(d[0]), "+f"(d[1]), "+f"(d[2]), "+f"(d[3])
                 : "r"(a[0]), "r"(a[1]), "r"(a[2]), "r"(a[3]), "r"(b[0]), "r"(b[1]));
}
__device__ __forceinline__ void cpasync16(uint32_t dst, const void* src) {
    asm volatile("cp.async.cg.shared.global [%0], [%1], 16;" :: "r"(dst), "l"(src));
}
#define CP_COMMIT() asm volatile("cp.async.commit_group;" ::: "memory")
#define CP_WAIT(n)  asm volatile("cp.async.wait_group %0;" :: "n"(n) : "memory")

__device__ __forceinline__ uint32_t swz_unit(int row, int u) {
    return (uint32_t)((row*4 + (u ^ ((row >> 1) & 3))) * 16);
}
__device__ __forceinline__ void split_bf16(float v, __nv_bfloat16& hi, __nv_bfloat16& lo) {
    hi = __float2bfloat16(v);
    lo = __float2bfloat16(v - __bfloat162float(hi));
}

#define STAGE_BYTES 32768
#define SMEM_TOTAL_MMA (STAGE_BYTES*3)   // 98304
#define GS_SMEM (3*256*33*4)             // 101376

// Shared GEMM inner machinery (128x128 tile, 8 warps 2x4, warp 64x32, 3 passes)
#define GEMM_COMPUTE(base_expr)                                                   \
    {                                                                             \
        const uint32_t base = (base_expr);                                        \
        _Pragma("unroll")                                                         \
        for (int ks = 0; ks < 2; ks++) {                                          \
            uint32_t a0[4][4], a1[4][4], bb0[4][2], bb1[4][2];                    \
            _Pragma("unroll")                                                     \
            for (int i = 0; i < 4; i++) {                                         \
                const int row = wm*64 + i*16 + (lane & 15);                       \
                const int u   = ks*2 + (lane >> 4);                               \
                ldsm4(a0[i], base + swz_unit(row, u));                            \
            }                                                                     \
            _Pragma("unroll")                                                     \
            for (int jj = 0; jj < 2; jj++) {                                      \
                const int row = wn*32 + jj*16 + ((lane >> 4) & 1)*8 + (lane & 7); \
                const int u   = ks*2 + ((lane >> 3) & 1);                         \
                uint32_t r[4];                                                    \
                ldsm4(r, base + 16384u + swz_unit(row, u));                       \
                bb0[jj*2+0][0] = r[0]; bb0[jj*2+0][1] = r[1];                     \
                bb0[jj*2+1][0] = r[2]; bb0[jj*2+1][1] = r[3];                     \
            }                                                                     \
            _Pragma("unroll")                                                     \
            for (int i = 0; i < 4; i++)                                           \
                _Pragma("unroll")                                                 \
                for (int j = 0; j < 4; j++)                                       \
                    mma16816(acc[i][j], a0[i], bb0[j]);                           \
            _Pragma("unroll")                                                     \
            for (int i = 0; i < 4; i++) {                                         \
                const int row = wm*64 + i*16 + (lane & 15);                       \
                const int u   = ks*2 + (lane >> 4);                               \
                ldsm4(a1[i], base + 8192u + swz_unit(row, u));                    \
            }                                                                     \
            _Pragma("unroll")                                                     \
            for (int i = 0; i < 4; i++)                                           \
                _Pragma("unroll")                                                 \
                for (int j = 0; j < 4; j++)                                       \
                    mma16816(acc[i][j], a1[i], bb0[j]);                           \
            _Pragma("unroll")                                                     \
            for (int jj = 0; jj < 2; jj++) {                                      \
                const int row = wn*32 + jj*16 + ((lane >> 4) & 1)*8 + (lane & 7); \
                const int u   = ks*2 + ((lane >> 3) & 1);                         \
                uint32_t r[4];                                                    \
                ldsm4(r, base + 24576u + swz_unit(row, u));                       \
                bb1[jj*2+0][0] = r[0]; bb1[jj*2+0][1] = r[1];                     \
                bb1[jj*2+1][0] = r[2]; bb1[jj*2+1][1] = r[3];                     \
            }                                                                     \
            _Pragma("unroll")                                                     \
            for (int i = 0; i < 4; i++)                                           \
                _Pragma("unroll")                                                 \
                for (int j = 0; j < 4; j++)                                       \
                    mma16816(acc[i][j], a0[i], bb1[j]);                           \
        }                                                                         \
    }

// ---------------------------------------------------------------- 1) GN stats
__global__ __launch_bounds__(256) void gn_stats_kernel(const float* __restrict__ x)
{
    const int bg  = blockIdx.x;
    const int tid = threadIdx.x;
    const float4* p4 = (const float4*)(x + (size_t)bg * 32 * HWN);
    float s = 0.f, s2 = 0.f;
    for (int i = tid; i < 32*HWN/4; i += 256) {
        float4 v = p4[i];
        s  += v.x + v.y + v.z + v.w;
        s2 += v.x*v.x + v.y*v.y + v.z*v.z + v.w*v.w;
    }
    __shared__ float rs[256], rs2[256];
    rs[tid] = s; rs2[tid] = s2;
    __syncthreads();
    for (int off = 128; off > 0; off >>= 1) {
        if (tid < off) { rs[tid] += rs[tid+off]; rs2[tid] += rs2[tid+off]; }
        __syncthreads();
    }
    if (tid == 0) {
        const float inv_n = 1.f / (float)(32*HWN);
        float mean = rs[0] * inv_n;
        float var  = rs2[0] * inv_n - mean*mean;
        g_mean[bg] = mean;
        g_rstd[bg] = rsqrtf(var + EPSV);
    }
}

// ---------------- 2) GN apply -> xnC hi/lo [c][n] and xnT hi/lo [n][c]
__global__ __launch_bounds__(256) void gn_apply_t_kernel(const float* __restrict__ x,
                                                         const float* __restrict__ nw,
                                                         const float* __restrict__ nb)
{
    const int nt = blockIdx.x, ct = blockIdx.y, b = blockIdx.z;
    const int n0 = nt*32, c0 = ct*32;
    __shared__ float tile[32][33];
    const int col = threadIdx.x & 31, r = threadIdx.x >> 5;
    #pragma unroll
    for (int p = 0; p < 4; p++) {
        int cl = r + p*8;
        int c = c0 + cl;
        float rstd = g_rstd[b*8 + (c >> 5)];
        float mean = g_mean[b*8 + (c >> 5)];
        float sw = nw[c]*rstd, sb2 = nb[c] - mean*sw;
        float v = x[((size_t)(b*CC_+c))*HWN + n0 + col];
        v = v*sw + sb2;
        tile[cl][col] = v;
        __nv_bfloat16 hi, lo; split_bf16(v, hi, lo);
        size_t cidx = ((size_t)(b*CC_+c))*HWN + n0 + col;
        g_xnC_hi[cidx] = hi; g_xnC_lo[cidx] = lo;
    }
    __syncthreads();
    #pragma unroll
    for (int p = 0; p < 4; p++) {
        int nl = r + p*8;
        float v = tile[col][nl];
        __nv_bfloat16 hi, lo; split_bf16(v, hi, lo);
        size_t idx = ((size_t)(b*HWN + n0 + nl))*CC_ + c0 + col;
        g_xnT_hi[idx] = hi; g_xnT_lo[idx] = lo;
    }
}

// ---------------------------------------------------------------- 3) weight preps
__global__ __launch_bounds__(256) void wprep_kernel(const float* __restrict__ qkv_w)
{
    const int i = blockIdx.x * 256 + threadIdx.x;
    if (i < 768*256) {
        __nv_bfloat16 hi, lo; split_bf16(qkv_w[i], hi, lo);
        g_wqkv_hi[i] = hi; g_wqkv_lo[i] = lo;
    }
}
__global__ __launch_bounds__(256) void wvt_prep_kernel(const float* __restrict__ qkv_w)
{
    const int c = blockIdx.x, cp = threadIdx.x;
    __nv_bfloat16 hi, lo; split_bf16(qkv_w[(512 + cp)*CC_ + c], hi, lo);
    g_wvT_hi[c*CC_ + cp] = hi; g_wvT_lo[c*CC_ + cp] = lo;
}

// ---------------------------------------------------------------- 4) s1 = row sums of xn
__global__ __launch_bounds__(256) void s1_kernel(const float* __restrict__ x,
                                                 const float* __restrict__ nw,
                                                 const float* __restrict__ nb)
{
    const int b = blockIdx.x;
    const int c = blockIdx.y*8 + (threadIdx.x >> 5);
    const int lane = threadIdx.x & 31;
    const float4* p = (const float4*)(x + ((size_t)(b*CC_+c))*HWN);
    float s = 0.f;
    for (int i = lane; i < HWN/4; i += 32) {
        float4 v = p[i];
        s += v.x + v.y + v.z + v.w;
    }
    #pragma unroll
    for (int o = 16; o > 0; o >>= 1) s += __shfl_xor_sync(0xffffffff, s, o);
    if (lane == 0) {
        float rstd = g_rstd[b*8 + (c >> 5)];
        float mean = g_mean[b*8 + (c >> 5)];
        float sw = nw[c]*rstd, sb2 = nb[c] - mean*sw;
        g_s1[b*CC_ + c] = s*sw + 4096.f*sb2;
    }
}

// ---------------- 5) S split-K GEMM: Spart[z] = xn[seg] xn[seg]^T (z=b*8+seg)
__global__ __launch_bounds__(256, 2) void s_gemm_kernel()
{
    extern __shared__ char smem[];
    const uint32_t sb = smem_u32(smem);
    const int tid = threadIdx.x;
    const int lane = tid & 31, wid = tid >> 5;
    const int wm = wid & 1, wn = wid >> 1;
    const int n0 = blockIdx.x * 128, m0 = blockIdx.y * 128;
    const int z = blockIdx.z, b = z >> 3, seg = z & 7;
    const int segoff = seg * 512;

    const __nv_bfloat16* Ahi = g_xnC_hi + (size_t)b*CC_*HWN;
    const __nv_bfloat16* Alo = g_xnC_lo + (size_t)b*CC_*HWN;

    float acc[4][4][4] = {};
    const int row_a = tid >> 2, u_a = tid & 3;

    auto load_chunk = [&](int chunk, int stage) {
        const int c0 = segoff + chunk * 32;
        const uint32_t base = sb + (uint32_t)stage * STAGE_BYTES;
        #pragma unroll
        for (int it = 0; it < 2; it++) {
            const int row = row_a + it*64;
            const uint32_t du = swz_unit(row, u_a);
            const size_t sa = (size_t)(m0 + row)*HWN + c0 + u_a*8;
            cpasync16(base +         du, Ahi + sa);
            cpasync16(base + 8192u + du, Alo + sa);
            const size_t sx = (size_t)(n0 + row)*HWN + c0 + u_a*8;
            cpasync16(base + 16384u + du, Ahi + sx);
            cpasync16(base + 24576u + du, Alo + sx);
        }
        CP_COMMIT();
    };

    load_chunk(0, 0);
    load_chunk(1, 1);
    for (int c = 0; c < 16; c++) {
        if (c < 15) CP_WAIT(1); else CP_WAIT(0);
        __syncthreads();
        if (c + 2 < 16) load_chunk(c + 2, (c + 2) % 3);
        GEMM_COMPUTE(sb + (uint32_t)(c % 3) * STAGE_BYTES);
    }

    float* dst = g_Spart + (size_t)z * 65536;
    #pragma unroll
    for (int i = 0; i < 4; i++)
        #pragma unroll
        for (int half = 0; half < 2; half++) {
            const int rl = m0 + wm*64 + i*16 + (lane >> 2) + half*8;
            #pragma unroll
            for (int j = 0; j < 4; j++) {
                const int cl = n0 + wn*32 + j*8 + (lane & 3)*2;
                float2 t = { acc[i][j][half*2+0], acc[i][j][half*2+1] };
                *(float2*)(dst + (size_t)rl*CC_ + cl) = t;
            }
        }
}

// ---------------------------------------------------------------- 6) reduce S partials
__global__ __launch_bounds__(256) void s_reduce_kernel()
{
    const size_t idx = (size_t)blockIdx.x * 256 + threadIdx.x;   // over 16*65536
    const int b = (int)(idx >> 16);
    const int rc = (int)(idx & 65535);
    float s = 0.f;
    #pragma unroll
    for (int seg = 0; seg < 8; seg++)
        s += g_Spart[((size_t)(b*8 + seg))*65536 + rc];
    __nv_bfloat16 hi, lo; split_bf16(s, hi, lo);
    g_S_hi[idx] = hi; g_S_lo[idx] = lo;
}

// ---------------- 7a) T = Wq * S  (globals referenced in device code!)
__global__ __launch_bounds__(256, 2) void t_gemm_kernel()
{
    extern __shared__ char smem[];
    const uint32_t sb = smem_u32(smem);
    const int tid = threadIdx.x;
    const int lane = tid & 31, wid = tid >> 5;
    const int wm = wid & 1, wn = wid >> 1;
    const int n0 = blockIdx.x * 128, m0 = blockIdx.y * 128, b = blockIdx.z;

    const __nv_bfloat16* Bhi = g_S_hi + (size_t)b*65536;
    const __nv_bfloat16* Blo = g_S_lo + (size_t)b*65536;

    float acc[4][4][4] = {};
    const int row_a = tid >> 2, u_a = tid & 3;

    auto load_chunk = [&](int chunk, int stage) {
        const int c0 = chunk * 32;
        const uint32_t base = sb + (uint32_t)stage * STAGE_BYTES;
        #pragma unroll
        for (int it = 0; it < 2; it++) {
            const int row = row_a + it*64;
            const uint32_t du = swz_unit(row, u_a);
            const size_t sa = (size_t)(m0 + row)*CC_ + c0 + u_a*8;
            cpasync16(base +         du, g_wqkv_hi + sa);
            cpasync16(base + 8192u + du, g_wqkv_lo + sa);
            const size_t sx = (size_t)(n0 + row)*CC_ + c0 + u_a*8;
            cpasync16(base + 16384u + du, Bhi + sx);
            cpasync16(base + 24576u + du, Blo + sx);
        }
        CP_COMMIT();
    };

    load_chunk(0, 0);
    load_chunk(1, 1);
    for (int c = 0; c < 8; c++) {
        if (c < 7) CP_WAIT(1); else CP_WAIT(0);
        __syncthreads();
        if (c + 2 < 8) load_chunk(c + 2, (c + 2) % 3);
        GEMM_COMPUTE(sb + (uint32_t)(c % 3) * STAGE_BYTES);
    }

    #pragma unroll
    for (int i = 0; i < 4; i++)
        #pragma unroll
        for (int half = 0; half < 2; half++) {
            const int rl = m0 + wm*64 + i*16 + (lane >> 2) + half*8;
            #pragma unroll
            for (int j = 0; j < 4; j++) {
                const int cl = n0 + wn*32 + j*8 + (lane & 3)*2;
                const size_t o = (size_t)b*65536 + (size_t)rl*CC_ + cl;
                *(float2*)(g_T + o) = make_float2(acc[i][j][half*2+0], acc[i][j][half*2+1]);
            }
        }
}

// ---------------- 7b) Weff = W~ * WvT  (globals referenced in device code!)
__global__ __launch_bounds__(256, 2) void weff_gemm_kernel()
{
    extern __shared__ char smem[];
    const uint32_t sb = smem_u32(smem);
    const int tid = threadIdx.x;
    const int lane = tid & 31, wid = tid >> 5;
    const int wm = wid & 1, wn = wid >> 1;
    const int n0 = blockIdx.x * 128, m0 = blockIdx.y * 128, b = blockIdx.z;

    const __nv_bfloat16* Ahi = g_wt_hi + (size_t)b*65536;
    const __nv_bfloat16* Alo = g_wt_lo + (size_t)b*65536;

    float acc[4][4][4] = {};
    const int row_a = tid >> 2, u_a = tid & 3;

    auto load_chunk = [&](int chunk, int stage) {
        const int c0 = chunk * 32;
        const uint32_t base = sb + (uint32_t)stage * STAGE_BYTES;
        #pragma unroll
        for (int it = 0; it < 2; it++) {
            const int row = row_a + it*64;
            const uint32_t du = swz_unit(row, u_a);
            const size_t sa = (size_t)(m0 + row)*CC_ + c0 + u_a*8;
            cpasync16(base +         du, Ahi + sa);
            cpasync16(base + 8192u + du, Alo + sa);
            const size_t sx = (size_t)(n0 + row)*CC_ + c0 + u_a*8;
            cpasync16(base + 16384u + du, g_wvT_hi + sx);
            cpasync16(base + 24576u + du, g_wvT_lo + sx);
        }
        CP_COMMIT();
    };

    load_chunk(0, 0);
    load_chunk(1, 1);
    for (int c = 0; c < 8; c++) {
        if (c < 7) CP_WAIT(1); else CP_WAIT(0);
        __syncthreads();
        if (c + 2 < 8) load_chunk(c + 2, (c + 2) % 3);
        GEMM_COMPUTE(sb + (uint32_t)(c % 3) * STAGE_BYTES);
    }

    #pragma unroll
    for (int i = 0; i < 4; i++)
        #pragma unroll
        for (int half = 0; half < 2; half++) {
            const int rl = m0 + wm*64 + i*16 + (lane >> 2) + half*8;
            #pragma unroll
            for (int j = 0; j < 4; j++) {
                const int cl = n0 + wn*32 + j*8 + (lane & 3)*2;
                const size_t o = (size_t)b*65536 + (size_t)rl*CC_ + cl;
                __nv_bfloat16 h0, l0, h1, l1;
                split_bf16(acc[i][j][half*2+0], h0, l0);
                split_bf16(acc[i][j][half*2+1], h1, l1);
                uint32_t hp = (uint32_t)*(uint16_t*)&h0 | ((uint32_t)*(uint16_t*)&h1 << 16);
                uint32_t lp = (uint32_t)*(uint16_t*)&l0 | ((uint32_t)*(uint16_t*)&l1 << 16);
                *(uint32_t*)(g_weff_hi + o) = hp;
                *(uint32_t*)(g_weff_lo + o) = lp;
            }
        }
}

// ---------------- 8) G assembly + softmax -> P (smem-tiled Wq/Wk/T)
__global__ __launch_bounds__(256) void gsoftmax_kernel(const float* __restrict__ qkv_w,
                                                       const float* __restrict__ qkv_b)
{
    extern __shared__ float sh[];        // 3 tiles [256][33]: Wk, T, Wq
    float* shWk = sh;
    float* shT  = sh + 256*33;
    float* shWq = sh + 2*256*33;
    const int b = blockIdx.x;
    const int tid = threadIdx.x;
    const int e = tid & 63, i = tid >> 6;
    const int r = i*64 + e;

    __shared__ float s1s[256];
    s1s[tid] = g_s1[b*CC_ + tid];

    float dT[4] = {}, ww[4] = {};
    float uu = 0.f;
    const float* Tb = g_T + (size_t)b*65536;

    for (int ct = 0; ct < 8; ct++) {
        const int c0 = ct*32;
        __syncthreads();
        for (int g = tid; g < 8192; g += 256) {
            const int row = g >> 5, cl = g & 31;
            shWk[row*33 + cl] = qkv_w[(size_t)(256 + row)*CC_ + c0 + cl];
            shT [row*33 + cl] = Tb[(size_t)row*CC_ + c0 + cl];
            shWq[row*33 + cl] = qkv_w[(size_t)row*CC_ + c0 + cl];
        }
        __syncthreads();
        #pragma unroll 4
        for (int cl = 0; cl < 32; cl++) {
            const float tc  = shT [r*33 + cl];
            const float s1c = s1s[c0 + cl];
            uu += shWq[r*33 + cl] * s1c;
            #pragma unroll
            for (int j = 0; j < 4; j++) {
                const float wk = shWk[(j*64 + e)*33 + cl];
                dT[j] += tc * wk;
                ww[j] += s1c * wk;
            }
        }
    }

    const float bq = qkv_b[r];
    float G[4];
    #pragma unroll
    for (int j = 0; j < 4; j++) {
        const float bk = qkv_b[256 + j*64 + e];
        G[j] = 0.125f * (dT[j] + bq*ww[j] + bk*uu + 4096.f*bq*bk);
    }
    float m = fmaxf(fmaxf(G[0], G[1]), fmaxf(G[2], G[3]));
    float e0 = expf(G[0]-m), e1 = expf(G[1]-m), e2 = expf(G[2]-m), e3 = expf(G[3]-m);
    float inv = 1.f / (e0+e1+e2+e3);
    float* P = g_P + ((size_t)(b*64 + e))*16 + i*4;
    P[0] = e0*inv; P[1] = e1*inv; P[2] = e2*inv; P[3] = e3*inv;
}

// ---------------- 9) W~ = fold proj_w with P (hi/lo)
__global__ __launch_bounds__(256) void wt_prep_kernel(const float* __restrict__ proj_w)
{
    const int o = blockIdx.x, b = blockIdx.y;
    const int c = threadIdx.x;
    const int e = c & 63, j = c >> 6;
    const float* P = g_P + ((size_t)(b*64 + e))*16 + j;
    float s = 0.f;
    #pragma unroll
    for (int i = 0; i < 4; i++)
        s += proj_w[o*CC_ + i*64 + e] * P[i*4];
    __nv_bfloat16 hi, lo; split_bf16(s, hi, lo);
    const size_t idx = ((size_t)b*CC_ + o)*CC_ + c;
    g_wt_hi[idx] = hi; g_wt_lo[idx] = lo;
}

// ---------------- 10) beff = W~ bv + pb
__global__ __launch_bounds__(256) void beff_kernel(const float* __restrict__ qkv_b,
                                                   const float* __restrict__ proj_b)
{
    const int b = blockIdx.x, o = threadIdx.x;
    const __nv_bfloat16* wh = g_wt_hi + ((size_t)b*CC_ + o)*CC_;
    const __nv_bfloat16* wl = g_wt_lo + ((size_t)b*CC_ + o)*CC_;
    float s = 0.f;
    for (int c = 0; c < CC_; c++)
        s += (__bfloat162float(wh[c]) + __bfloat162float(wl[c])) * qkv_b[512 + c];
    g_beff[b*CC_ + o] = s + proj_b[o];
}

// ---------------- 11) final GEMM: out = Weff xn + beff + x
__global__ __launch_bounds__(256, 2) void final_gemm_kernel(const float* __restrict__ xres,
                                                            float* __restrict__ out)
{
    extern __shared__ char smem[];
    const uint32_t sb = smem_u32(smem);
    const int tid = threadIdx.x;
    const int lane = tid & 31, wid = tid >> 5;
    const int wm = wid & 1, wn = wid >> 1;
    const int n0 = blockIdx.x * 128, m0 = blockIdx.y * 128, b = blockIdx.z;

    const __nv_bfloat16* Whi = g_weff_hi + (size_t)b * 65536;
    const __nv_bfloat16* Wlo = g_weff_lo + (size_t)b * 65536;

    float acc[4][4][4] = {};
    const int row_a = tid >> 2, u_a = tid & 3;

    auto load_chunk = [&](int chunk, int stage) {
        const int c0 = chunk * 32;
        const uint32_t base = sb + (uint32_t)stage * STAGE_BYTES;
        #pragma unroll
        for (int it = 0; it < 2; it++) {
            const int row = row_a + it*64;
            const uint32_t du = swz_unit(row, u_a);
            const size_t sa = (size_t)(m0 + row)*CC_ + c0 + u_a*8;
            cpasync16(base +         du, Whi + sa);
            cpasync16(base + 8192u + du, Wlo + sa);
            const size_t sx = (size_t)(b*HWN + n0 + row)*CC_ + c0 + u_a*8;
            cpasync16(base + 16384u + du, g_xnT_hi + sx);
            cpasync16(base + 24576u + du, g_xnT_lo + sx);
        }
        CP_COMMIT();
    };

    load_chunk(0, 0);
    load_chunk(1, 1);
    for (int c = 0; c < 8; c++) {
        if (c < 7) CP_WAIT(1); else CP_WAIT(0);
        __syncthreads();
        if (c + 2 < 8) load_chunk(c + 2, (c + 2) % 3);
        GEMM_COMPUTE(sb + (uint32_t)(c % 3) * STAGE_BYTES);
    }

    #pragma unroll
    for (int i = 0; i < 4; i++)
        #pragma unroll
        for (int half = 0; half < 2; half++) {
            const int o = m0 + wm*64 + i*16 + (lane >> 2) + half*8;
            const float bv = g_beff[b*CC_ + o];
            const size_t off = ((size_t)(b*CC_ + o))*HWN + n0;
            #pragma unroll
            for (int j = 0; j < 4; j++) {
                const int col = wn*32 + j*8 + (lane & 3)*2;
                float2 xv = *(const float2*)(xres + off + col);
                float2 t;
                t.x = acc[i][j][half*2+0] + bv + xv.x;
                t.y = acc[i][j][half*2+1] + bv + xv.y;
                *(float2*)(out + off + col) = t;
            }
        }
}

// ---------------------------------------------------------------- launch
extern "C" void kernel_launch(void* const* d_in, const int* in_sizes, int n_in,
                              void* d_out, int out_size)
{
    const float* x      = (const float*)d_in[0];
    const float* norm_w = (const float*)d_in[1];
    const float* norm_b = (const float*)d_in[2];
    const float* qkv_w  = (const float*)d_in[3];
    const float* qkv_b  = (const float*)d_in[4];
    const float* proj_w = (const float*)d_in[5];
    const float* proj_b = (const float*)d_in[6];
    float* out = (float*)d_out;

    static bool attr_set = false;
    if (!attr_set) {
        cudaFuncSetAttribute(s_gemm_kernel,
                             cudaFuncAttributeMaxDynamicSharedMemorySize, SMEM_TOTAL_MMA);
        cudaFuncSetAttribute(t_gemm_kernel,
                             cudaFuncAttributeMaxDynamicSharedMemorySize, SMEM_TOTAL_MMA);
        cudaFuncSetAttribute(weff_gemm_kernel,
                             cudaFuncAttributeMaxDynamicSharedMemorySize, SMEM_TOTAL_MMA);
        cudaFuncSetAttribute(final_gemm_kernel,
                             cudaFuncAttributeMaxDynamicSharedMemorySize, SMEM_TOTAL_MMA);
        cudaFuncSetAttribute(gsoftmax_kernel,
                             cudaFuncAttributeMaxDynamicSharedMemorySize, GS_SMEM);
        attr_set = true;
    }

    gn_stats_kernel<<<BB*8, 256>>>(x);
    wprep_kernel<<<768, 256>>>(qkv_w);
    wvt_prep_kernel<<<256, 256>>>(qkv_w);
    gn_apply_t_kernel<<<dim3(128, 8, BB), 256>>>(x, norm_w, norm_b);
    s1_kernel<<<dim3(BB, 32), 256>>>(x, norm_w, norm_b);
    s_gemm_kernel<<<dim3(2, 2, 128), 256, SMEM_TOTAL_MMA>>>();
    s_reduce_kernel<<<4096, 256>>>();
    t_gemm_kernel<<<dim3(2, 2, BB), 256, SMEM_TOTAL_MMA>>>();
    gsoftmax_kernel<<<BB, 256, GS_SMEM>>>(qkv_w, qkv_b);
    wt_prep_kernel<<<dim3(CC_, BB), 256>>>(proj_w);
    weff_gemm_kernel<<<dim3(2, 2, BB), 256, SMEM_TOTAL_MMA>>>();
    beff_kernel<<<BB, 256>>>(qkv_b, proj_b);
    final_gemm_kernel<<<dim3(32, 2, BB), 256, SMEM_TOTAL_MMA>>>(x, out);
}

// round 16
// speedup vs baseline: 1.5068x; 1.5068x over previous
#include <cuda_runtime.h>
#include <cuda_bf16.h>
#include <cstdint>

// ---------------------------------------------------------------- constants
#define BB 16
#define CC_ 256
#define HWN 4096
#define EPSV 1e-5f
#define TOTAL (BB*CC_*HWN)   // 16,777,216

// ---------------------------------------------------------------- scratch
__device__ __nv_bfloat16 g_xnT_hi[TOTAL];      // [b][n][c]
__device__ __nv_bfloat16 g_xnT_lo[TOTAL];
__device__ __nv_bfloat16 g_xnC_hi[TOTAL];      // [b][c][n]
__device__ __nv_bfloat16 g_xnC_lo[TOTAL];
__device__ __nv_bfloat16 g_wqkv_hi[768*256];
__device__ __nv_bfloat16 g_wqkv_lo[768*256];
__device__ __nv_bfloat16 g_wvT_hi[256*256];    // WvT[c][c'] = Wv[c'][c]
__device__ __nv_bfloat16 g_wvT_lo[256*256];
__device__ float g_Spart[128*3*16384];         // [z][blk:D0,D1,O][128][128]
__device__ __nv_bfloat16 g_S_hi[BB*256*256];
__device__ __nv_bfloat16 g_S_lo[BB*256*256];
__device__ __nv_bfloat16 g_T_hi[BB*256*256];   // T = Wq * S (bf16 hi/lo)
__device__ __nv_bfloat16 g_T_lo[BB*256*256];
__device__ float g_M[BB*256*256];              // M = T * Wk^T
__device__ float g_uw[BB*512];                 // [b][r<256: Wq.s1 | r>=256: Wk.s1]
__device__ float g_s1[BB*256];
__device__ float g_P[BB*64*16];
__device__ __nv_bfloat16 g_wt_hi[BB*256*256];  // W~ (P-folded proj)
__device__ __nv_bfloat16 g_wt_lo[BB*256*256];
__device__ __nv_bfloat16 g_weff_hi[BB*256*256];
__device__ __nv_bfloat16 g_weff_lo[BB*256*256];
__device__ float g_beff[BB*256];
__device__ float g_mean[BB*8];
__device__ float g_rstd[BB*8];

// ---------------------------------------------------------------- PTX helpers
__device__ __forceinline__ uint32_t smem_u32(const void* p) {
    uint32_t a;
    asm("{ .reg .u64 t; cvta.to.shared.u64 t, %1; cvt.u32.u64 %0, t; }" : "=r"(a) : "l"(p));
    return a;
}
__device__ __forceinline__ void ldsm4(uint32_t* r, uint32_t addr) {
    asm volatile("ldmatrix.sync.aligned.m8n8.x4.shared.b16 {%0,%1,%2,%3}, [%4];"
                 : "=r"(r[0]), "=r"(r[1]), "=r"(r[2]), "=r"(r[3]) : "r"(addr));
}
__device__ __forceinline__ void mma16816(float* d, const uint32_t* a, const uint32_t* b) {
    asm volatile("mma.sync.aligned.m16n8k16.row.col.f32.bf16.bf16.f32 "
                 "{%0,%1,%2,%3}, {%4,%5,%6,%7}, {%8,%9}, {%0,%1,%2,%3};"
                 : "+f"(d[0]), "+f"(d[1]), "+f"(d[2]), "+f"(d[3])
                 : "r"(a[0]), "r"(a[1]), "r"(a[2]), "r"(a[3]), "r"(b[0]), "r"(b[1]));
}
__device__ __forceinline__ void cpasync16(uint32_t dst, const void* src) {
    asm volatile("cp.async.cg.shared.global [%0], [%1], 16;" :: "r"(dst), "l"(src));
}
#define CP_COMMIT() asm volatile("cp.async.commit_group;" ::: "memory")
#define CP_WAIT(n)  asm volatile("cp.async.wait_group %0;" :: "n"(n) : "memory")

__device__ __forceinline__ uint32_t swz_unit(int row, int u) {
    return (uint32_t)((row*4 + (u ^ ((row >> 1) & 3))) * 16);
}
__device__ __forceinline__ void split_bf16(float v, __nv_bfloat16& hi, __nv_bfloat16& lo) {
    hi = __float2bfloat16(v);
    lo = __float2bfloat16(v - __bfloat162float(hi));
}

#define STAGE_BYTES 32768
#define SMEM_TOTAL_MMA (STAGE_BYTES*3)   // 98304

// GEMM inner machinery with separate A/B smem bases.
// A hi @ab, A lo @ab+8192; B hi @bb, B lo @bb+8192.
#define GEMM_COMPUTE2(ab_expr, bb_expr)                                           \
    {                                                                             \
        const uint32_t ab = (ab_expr);                                            \
        const uint32_t bb = (bb_expr);                                            \
        _Pragma("unroll")                                                         \
        for (int ks = 0; ks < 2; ks++) {                                          \
            uint32_t a0[4][4], a1[4][4], bb0[4][2], bb1[4][2];                    \
            _Pragma("unroll")                                                     \
            for (int i = 0; i < 4; i++) {                                         \
                const int row = wm*64 + i*16 + (lane & 15);                       \
                const int u   = ks*2 + (lane >> 4);                               \
                ldsm4(a0[i], ab + swz_unit(row, u));                              \
            }                                                                     \
            _Pragma("unroll")                                                     \
            for (int jj = 0; jj < 2; jj++) {                                      \
                const int row = wn*32 + jj*16 + ((lane >> 4) & 1)*8 + (lane & 7); \
                const int u   = ks*2 + ((lane >> 3) & 1);                         \
                uint32_t r[4];                                                    \
                ldsm4(r, bb + swz_unit(row, u));                                  \
                bb0[jj*2+0][0] = r[0]; bb0[jj*2+0][1] = r[1];                     \
                bb0[jj*2+1][0] = r[2]; bb0[jj*2+1][1] = r[3];                     \
            }                                                                     \
            _Pragma("unroll")                                                     \
            for (int i = 0; i < 4; i++)                                           \
                _Pragma("unroll")                                                 \
                for (int j = 0; j < 4; j++)                                       \
                    mma16816(acc[i][j], a0[i], bb0[j]);                           \
            _Pragma("unroll")                                                     \
            for (int i = 0; i < 4; i++) {                                         \
                const int row = wm*64 + i*16 + (lane & 15);                       \
                const int u   = ks*2 + (lane >> 4);                               \
                ldsm4(a1[i], ab + 8192u + swz_unit(row, u));                      \
            }                                                                     \
            _Pragma("unroll")                                                     \
            for (int i = 0; i < 4; i++)                                           \
                _Pragma("unroll")                                                 \
                for (int j = 0; j < 4; j++)                                       \
                    mma16816(acc[i][j], a1[i], bb0[j]);                           \
            _Pragma("unroll")                                                     \
            for (int jj = 0; jj < 2; jj++) {                                      \
                const int row = wn*32 + jj*16 + ((lane >> 4) & 1)*8 + (lane & 7); \
                const int u   = ks*2 + ((lane >> 3) & 1);                         \
                uint32_t r[4];                                                    \
                ldsm4(r, bb + 8192u + swz_unit(row, u));                          \
                bb1[jj*2+0][0] = r[0]; bb1[jj*2+0][1] = r[1];                     \
                bb1[jj*2+1][0] = r[2]; bb1[jj*2+1][1] = r[3];                     \
            }                                                                     \
            _Pragma("unroll")                                                     \
            for (int i = 0; i < 4; i++)                                           \
                _Pragma("unroll")                                                 \
                for (int j = 0; j < 4; j++)                                       \
                    mma16816(acc[i][j], a0[i], bb1[j]);                           \
        }                                                                         \
    }

// ---------------------------------------------------------------- 1) GN stats
__global__ __launch_bounds__(256) void gn_stats_kernel(const float* __restrict__ x)
{
    const int bg  = blockIdx.x;
    const int tid = threadIdx.x;
    const float4* p4 = (const float4*)(x + (size_t)bg * 32 * HWN);
    float s = 0.f, s2 = 0.f;
    for (int i = tid; i < 32*HWN/4; i += 256) {
        float4 v = p4[i];
        s  += v.x + v.y + v.z + v.w;
        s2 += v.x*v.x + v.y*v.y + v.z*v.z + v.w*v.w;
    }
    __shared__ float rs[256], rs2[256];
    rs[tid] = s; rs2[tid] = s2;
    __syncthreads();
    for (int off = 128; off > 0; off >>= 1) {
        if (tid < off) { rs[tid] += rs[tid+off]; rs2[tid] += rs2[tid+off]; }
        __syncthreads();
    }
    if (tid == 0) {
        const float inv_n = 1.f / (float)(32*HWN);
        float mean = rs[0] * inv_n;
        float var  = rs2[0] * inv_n - mean*mean;
        g_mean[bg] = mean;
        g_rstd[bg] = rsqrtf(var + EPSV);
    }
}

// ---------------- 2) GN apply -> xnC hi/lo [c][n] and xnT hi/lo [n][c]
__global__ __launch_bounds__(256) void gn_apply_t_kernel(const float* __restrict__ x,
                                                         const float* __restrict__ nw,
                                                         const float* __restrict__ nb)
{
    const int nt = blockIdx.x, ct = blockIdx.y, b = blockIdx.z;
    const int n0 = nt*32, c0 = ct*32;
    __shared__ float tile[32][33];
    const int col = threadIdx.x & 31, r = threadIdx.x >> 5;
    #pragma unroll
    for (int p = 0; p < 4; p++) {
        int cl = r + p*8;
        int c = c0 + cl;
        float rstd = g_rstd[b*8 + (c >> 5)];
        float mean = g_mean[b*8 + (c >> 5)];
        float sw = nw[c]*rstd, sb2 = nb[c] - mean*sw;
        float v = x[((size_t)(b*CC_+c))*HWN + n0 + col];
        v = v*sw + sb2;
        tile[cl][col] = v;
        __nv_bfloat16 hi, lo; split_bf16(v, hi, lo);
        size_t cidx = ((size_t)(b*CC_+c))*HWN + n0 + col;
        g_xnC_hi[cidx] = hi; g_xnC_lo[cidx] = lo;
    }
    __syncthreads();
    #pragma unroll
    for (int p = 0; p < 4; p++) {
        int nl = r + p*8;
        float v = tile[col][nl];
        __nv_bfloat16 hi, lo; split_bf16(v, hi, lo);
        size_t idx = ((size_t)(b*HWN + n0 + nl))*CC_ + c0 + col;
        g_xnT_hi[idx] = hi; g_xnT_lo[idx] = lo;
    }
}

// ---------------------------------------------------------------- 3) weight preps
__global__ __launch_bounds__(256) void wprep_kernel(const float* __restrict__ qkv_w)
{
    const int i = blockIdx.x * 256 + threadIdx.x;
    if (i < 768*256) {
        __nv_bfloat16 hi, lo; split_bf16(qkv_w[i], hi, lo);
        g_wqkv_hi[i] = hi; g_wqkv_lo[i] = lo;
    }
}
__global__ __launch_bounds__(256) void wvt_prep_kernel(const float* __restrict__ qkv_w)
{
    const int c = blockIdx.x, cp = threadIdx.x;
    __nv_bfloat16 hi, lo; split_bf16(qkv_w[(512 + cp)*CC_ + c], hi, lo);
    g_wvT_hi[c*CC_ + cp] = hi; g_wvT_lo[c*CC_ + cp] = lo;
}

// ---------------------------------------------------------------- 4) s1 = row sums of xn
__global__ __launch_bounds__(256) void s1_kernel(const float* __restrict__ x,
                                                 const float* __restrict__ nw,
                                                 const float* __restrict__ nb)
{
    const int b = blockIdx.x;
    const int c = blockIdx.y*8 + (threadIdx.x >> 5);
    const int lane = threadIdx.x & 31;
    const float4* p = (const float4*)(x + ((size_t)(b*CC_+c))*HWN);
    float s = 0.f;
    for (int i = lane; i < HWN/4; i += 32) {
        float4 v = p[i];
        s += v.x + v.y + v.z + v.w;
    }
    #pragma unroll
    for (int o = 16; o > 0; o >>= 1) s += __shfl_xor_sync(0xffffffff, s, o);
    if (lane == 0) {
        float rstd = g_rstd[b*8 + (c >> 5)];
        float mean = g_mean[b*8 + (c >> 5)];
        float sw = nw[c]*rstd, sb2 = nb[c] - mean*sw;
        g_s1[b*CC_ + c] = s*sw + 4096.f*sb2;
    }
}

// ---------------- 5) S symmetric split-K GEMM.
// grid (3, 1, 128): z = b*8+seg; tile t: 0=D0(0,0) 1=D1(128,128) 2=O(0,128).
// Diag tiles load only A rows and alias B smem onto A. Output 128x128 block
// to g_Spart[z][t].
__global__ __launch_bounds__(256, 2) void s_gemm_kernel()
{
    extern __shared__ char smem[];
    const uint32_t sb = smem_u32(smem);
    const int tid = threadIdx.x;
    const int lane = tid & 31, wid = tid >> 5;
    const int wm = wid & 1, wn = wid >> 1;
    const int t = blockIdx.x;
    const int z = blockIdx.z, b = z >> 3, seg = z & 7;
    const int segoff = seg * 512;
    const int m0 = (t == 1) ? 128 : 0;
    const int n0 = (t == 0) ? 0 : 128;
    const bool diag = (t < 2);

    const __nv_bfloat16* Ahi = g_xnC_hi + (size_t)b*CC_*HWN;
    const __nv_bfloat16* Alo = g_xnC_lo + (size_t)b*CC_*HWN;

    float acc[4][4][4] = {};
    const int row_a = tid >> 2, u_a = tid & 3;

    auto load_chunk = [&](int chunk, int stage) {
        const int c0 = segoff + chunk * 32;
        const uint32_t base = sb + (uint32_t)stage * STAGE_BYTES;
        #pragma unroll
        for (int it = 0; it < 2; it++) {
            const int row = row_a + it*64;
            const uint32_t du = swz_unit(row, u_a);
            const size_t sa = (size_t)(m0 + row)*HWN + c0 + u_a*8;
            cpasync16(base +         du, Ahi + sa);
            cpasync16(base + 8192u + du, Alo + sa);
            if (!diag) {
                const size_t sx = (size_t)(n0 + row)*HWN + c0 + u_a*8;
                cpasync16(base + 16384u + du, Ahi + sx);
                cpasync16(base + 24576u + du, Alo + sx);
            }
        }
        CP_COMMIT();
    };

    load_chunk(0, 0);
    load_chunk(1, 1);
    for (int c = 0; c < 16; c++) {
        if (c < 15) CP_WAIT(1); else CP_WAIT(0);
        __syncthreads();
        if (c + 2 < 16) load_chunk(c + 2, (c + 2) % 3);
        const uint32_t stg = sb + (uint32_t)(c % 3) * STAGE_BYTES;
        if (diag) {
            GEMM_COMPUTE2(stg, stg);
        } else {
            GEMM_COMPUTE2(stg, stg + 16384u);
        }
    }

    float* dst = g_Spart + ((size_t)z*3 + t)*16384;
    #pragma unroll
    for (int i = 0; i < 4; i++)
        #pragma unroll
        for (int half = 0; half < 2; half++) {
            const int rl = wm*64 + i*16 + (lane >> 2) + half*8;
            #pragma unroll
            for (int j = 0; j < 4; j++) {
                const int cl = wn*32 + j*8 + (lane & 3)*2;
                float2 v = { acc[i][j][half*2+0], acc[i][j][half*2+1] };
                *(float2*)(dst + rl*128 + cl) = v;
            }
        }
}

// ---------------- 6) reduce S partials (+ reconstruct lower-left by transpose)
// grid (8 tilesC, 8 tilesR, BB). Each block: 32x32 output tile, sum 8 segs.
__global__ __launch_bounds__(256) void s_reduce_kernel()
{
    const int tC = blockIdx.x, tR = blockIdx.y, b = blockIdx.z;
    const int col = threadIdx.x & 31, r = threadIdx.x >> 5;
    const bool trans = (tR >= 4 && tC < 4);
    int blk, sR0, sC0;
    if (tR < 4 && tC < 4)        { blk = 0; sR0 = tR*32;       sC0 = tC*32; }
    else if (tR >= 4 && tC >= 4) { blk = 1; sR0 = tR*32 - 128; sC0 = tC*32 - 128; }
    else if (!trans)             { blk = 2; sR0 = tR*32;       sC0 = tC*32 - 128; }
    else                         { blk = 2; sR0 = tC*32;       sC0 = tR*32 - 128; }

    float acc[4] = {};
    if (!trans) {
        #pragma unroll
        for (int seg = 0; seg < 8; seg++) {
            const float* src = g_Spart + ((size_t)(b*8 + seg)*3 + blk)*16384;
            #pragma unroll
            for (int p = 0; p < 4; p++)
                acc[p] += src[(sR0 + r + p*8)*128 + sC0 + col];
        }
    } else {
        __shared__ float sm[32][33];
        #pragma unroll
        for (int seg = 0; seg < 8; seg++) {
            const float* src = g_Spart + ((size_t)(b*8 + seg)*3 + blk)*16384;
            __syncthreads();
            #pragma unroll
            for (int p = 0; p < 4; p++)
                sm[r + p*8][col] = src[(sR0 + r + p*8)*128 + sC0 + col];
            __syncthreads();
            #pragma unroll
            for (int p = 0; p < 4; p++)
                acc[p] += sm[col][r + p*8];
        }
    }
    #pragma unroll
    for (int p = 0; p < 4; p++) {
        const int c1 = tR*32 + r + p*8, c2 = tC*32 + col;
        const size_t idx = (size_t)b*65536 + (size_t)c1*CC_ + c2;
        __nv_bfloat16 hi, lo; split_bf16(acc[p], hi, lo);
        g_S_hi[idx] = hi; g_S_lo[idx] = lo;
    }
}

// ---------------- 7a) T = Wq * S -> bf16 hi/lo
__global__ __launch_bounds__(256, 2) void t_gemm_kernel()
{
    extern __shared__ char smem[];
    const uint32_t sb = smem_u32(smem);
    const int tid = threadIdx.x;
    const int lane = tid & 31, wid = tid >> 5;
    const int wm = wid & 1, wn = wid >> 1;
    const int n0 = blockIdx.x * 128, m0 = blockIdx.y * 128, b = blockIdx.z;

    const __nv_bfloat16* Bhi = g_S_hi + (size_t)b*65536;
    const __nv_bfloat16* Blo = g_S_lo + (size_t)b*65536;

    float acc[4][4][4] = {};
    const int row_a = tid >> 2, u_a = tid & 3;

    auto load_chunk = [&](int chunk, int stage) {
        const int c0 = chunk * 32;
        const uint32_t base = sb + (uint32_t)stage * STAGE_BYTES;
        #pragma unroll
        for (int it = 0; it < 2; it++) {
            const int row = row_a + it*64;
            const uint32_t du = swz_unit(row, u_a);
            const size_t sa = (size_t)(m0 + row)*CC_ + c0 + u_a*8;
            cpasync16(base +         du, g_wqkv_hi + sa);
            cpasync16(base + 8192u + du, g_wqkv_lo + sa);
            const size_t sx = (size_t)(n0 + row)*CC_ + c0 + u_a*8;
            cpasync16(base + 16384u + du, Bhi + sx);
            cpasync16(base + 24576u + du, Blo + sx);
        }
        CP_COMMIT();
    };

    load_chunk(0, 0);
    load_chunk(1, 1);
    for (int c = 0; c < 8; c++) {
        if (c < 7) CP_WAIT(1); else CP_WAIT(0);
        __syncthreads();
        if (c + 2 < 8) load_chunk(c + 2, (c + 2) % 3);
        const uint32_t stg = sb + (uint32_t)(c % 3) * STAGE_BYTES;
        GEMM_COMPUTE2(stg, stg + 16384u);
    }

    #pragma unroll
    for (int i = 0; i < 4; i++)
        #pragma unroll
        for (int half = 0; half < 2; half++) {
            const int rl = m0 + wm*64 + i*16 + (lane >> 2) + half*8;
            #pragma unroll
            for (int j = 0; j < 4; j++) {
                const int cl = n0 + wn*32 + j*8 + (lane & 3)*2;
                const size_t o = (size_t)b*65536 + (size_t)rl*CC_ + cl;
                __nv_bfloat16 h0, l0, h1, l1;
                split_bf16(acc[i][j][half*2+0], h0, l0);
                split_bf16(acc[i][j][half*2+1], h1, l1);
                uint32_t hp = (uint32_t)*(uint16_t*)&h0 | ((uint32_t)*(uint16_t*)&h1 << 16);
                uint32_t lp = (uint32_t)*(uint16_t*)&l0 | ((uint32_t)*(uint16_t*)&l1 << 16);
                *(uint32_t*)(g_T_hi + o) = hp;
                *(uint32_t*)(g_T_lo + o) = lp;
            }
        }
}

// ---------------- 7b) M = T * Wk^T -> fp32
__global__ __launch_bounds__(256, 2) void m_gemm_kernel()
{
    extern __shared__ char smem[];
    const uint32_t sb = smem_u32(smem);
    const int tid = threadIdx.x;
    const int lane = tid & 31, wid = tid >> 5;
    const int wm = wid & 1, wn = wid >> 1;
    const int n0 = blockIdx.x * 128, m0 = blockIdx.y * 128, b = blockIdx.z;

    const __nv_bfloat16* Ahi = g_T_hi + (size_t)b*65536;
    const __nv_bfloat16* Alo = g_T_lo + (size_t)b*65536;
    const __nv_bfloat16* Bhi = g_wqkv_hi + 256*256;   // Wk rows
    const __nv_bfloat16* Blo = g_wqkv_lo + 256*256;

    float acc[4][4][4] = {};
    const int row_a = tid >> 2, u_a = tid & 3;

    auto load_chunk = [&](int chunk, int stage) {
        const int c0 = chunk * 32;
        const uint32_t base = sb + (uint32_t)stage * STAGE_BYTES;
        #pragma unroll
        for (int it = 0; it < 2; it++) {
            const int row = row_a + it*64;
            const uint32_t du = swz_unit(row, u_a);
            const size_t sa = (size_t)(m0 + row)*CC_ + c0 + u_a*8;
            cpasync16(base +         du, Ahi + sa);
            cpasync16(base + 8192u + du, Alo + sa);
            const size_t sx = (size_t)(n0 + row)*CC_ + c0 + u_a*8;
            cpasync16(base + 16384u + du, Bhi + sx);
            cpasync16(base + 24576u + du, Blo + sx);
        }
        CP_COMMIT();
    };

    load_chunk(0, 0);
    load_chunk(1, 1);
    for (int c = 0; c < 8; c++) {
        if (c < 7) CP_WAIT(1); else CP_WAIT(0);
        __syncthreads();
        if (c + 2 < 8) load_chunk(c + 2, (c + 2) % 3);
        const uint32_t stg = sb + (uint32_t)(c % 3) * STAGE_BYTES;
        GEMM_COMPUTE2(stg, stg + 16384u);
    }

    #pragma unroll
    for (int i = 0; i < 4; i++)
        #pragma unroll
        for (int half = 0; half < 2; half++) {
            const int rl = m0 + wm*64 + i*16 + (lane >> 2) + half*8;
            #pragma unroll
            for (int j = 0; j < 4; j++) {
                const int cl = n0 + wn*32 + j*8 + (lane & 3)*2;
                const size_t o = (size_t)b*65536 + (size_t)rl*CC_ + cl;
                *(float2*)(g_M + o) = make_float2(acc[i][j][half*2+0], acc[i][j][half*2+1]);
            }
        }
}

// ---------------- 8a) uw[b][r] = qkv_w[r] . s1[b]  (r in [0,512))
__global__ __launch_bounds__(256) void uw_kernel(const float* __restrict__ qkv_w)
{
    const int b = blockIdx.y;
    const int rr = blockIdx.x*8 + (threadIdx.x >> 5);
    const int lane = threadIdx.x & 31;
    const float* w = qkv_w + (size_t)rr*CC_;
    const float* s = g_s1 + b*CC_;
    float acc = 0.f;
    #pragma unroll
    for (int k = 0; k < 8; k++)
        acc += w[lane + k*32] * s[lane + k*32];
    #pragma unroll
    for (int o = 16; o > 0; o >>= 1) acc += __shfl_xor_sync(0xffffffff, acc, o);
    if (lane == 0) g_uw[b*512 + rr] = acc;
}

// ---------------- 8b) softmax extract -> P
__global__ __launch_bounds__(256) void psoftmax_kernel(const float* __restrict__ qkv_b)
{
    const int b = blockIdx.x;
    const int tid = threadIdx.x;
    const int e = tid & 63, i = tid >> 6;
    const int r = i*64 + e;
    const float bq = qkv_b[r];
    const float uu = g_uw[b*512 + r];
    float G[4];
    #pragma unroll
    for (int j = 0; j < 4; j++) {
        const int r2 = j*64 + e;
        const float bk = qkv_b[256 + r2];
        const float ww = g_uw[b*512 + 256 + r2];
        const float Mv = g_M[(size_t)b*65536 + (size_t)r*CC_ + r2];
        G[j] = 0.125f * (Mv + bq*ww + bk*uu + 4096.f*bq*bk);
    }
    float m = fmaxf(fmaxf(G[0], G[1]), fmaxf(G[2], G[3]));
    float e0 = expf(G[0]-m), e1 = expf(G[1]-m), e2 = expf(G[2]-m), e3 = expf(G[3]-m);
    float inv = 1.f / (e0+e1+e2+e3);
    float* P = g_P + ((size_t)(b*64 + e))*16 + i*4;
    P[0] = e0*inv; P[1] = e1*inv; P[2] = e2*inv; P[3] = e3*inv;
}

// ---------------- 9) W~ = fold proj_w with P (hi/lo) + fused beff reduction
__global__ __launch_bounds__(256) void wt_prep_kernel(const float* __restrict__ proj_w,
                                                      const float* __restrict__ qkv_b,
                                                      const float* __restrict__ proj_b)
{
    const int o = blockIdx.x, b = blockIdx.y;
    const int c = threadIdx.x;
    const int e = c & 63, j = c >> 6;
    const float* P = g_P + ((size_t)(b*64 + e))*16 + j;
    float s = 0.f;
    #pragma unroll
    for (int i = 0; i < 4; i++)
        s += proj_w[o*CC_ + i*64 + e] * P[i*4];
    __nv_bfloat16 hi, lo; split_bf16(s, hi, lo);
    const size_t idx = ((size_t)b*CC_ + o)*CC_ + c;
    g_wt_hi[idx] = hi; g_wt_lo[idx] = lo;

    __shared__ float red[256];
    red[c] = s * qkv_b[512 + c];
    __syncthreads();
    for (int off = 128; off > 0; off >>= 1) {
        if (c < off) red[c] += red[c + off];
        __syncthreads();
    }
    if (c == 0) g_beff[b*CC_ + o] = red[0] + proj_b[o];
}

// ---------------- 10) Weff = W~ * WvT
__global__ __launch_bounds__(256, 2) void weff_gemm_kernel()
{
    extern __shared__ char smem[];
    const uint32_t sb = smem_u32(smem);
    const int tid = threadIdx.x;
    const int lane = tid & 31, wid = tid >> 5;
    const int wm = wid & 1, wn = wid >> 1;
    const int n0 = blockIdx.x * 128, m0 = blockIdx.y * 128, b = blockIdx.z;

    const __nv_bfloat16* Ahi = g_wt_hi + (size_t)b*65536;
    const __nv_bfloat16* Alo = g_wt_lo + (size_t)b*65536;

    float acc[4][4][4] = {};
    const int row_a = tid >> 2, u_a = tid & 3;

    auto load_chunk = [&](int chunk, int stage) {
        const int c0 = chunk * 32;
        const uint32_t base = sb + (uint32_t)stage * STAGE_BYTES;
        #pragma unroll
        for (int it = 0; it < 2; it++) {
            const int row = row_a + it*64;
            const uint32_t du = swz_unit(row, u_a);
            const size_t sa = (size_t)(m0 + row)*CC_ + c0 + u_a*8;
            cpasync16(base +         du, Ahi + sa);
            cpasync16(base + 8192u + du, Alo + sa);
            const size_t sx = (size_t)(n0 + row)*CC_ + c0 + u_a*8;
            cpasync16(base + 16384u + du, g_wvT_hi + sx);
            cpasync16(base + 24576u + du, g_wvT_lo + sx);
        }
        CP_COMMIT();
    };

    load_chunk(0, 0);
    load_chunk(1, 1);
    for (int c = 0; c < 8; c++) {
        if (c < 7) CP_WAIT(1); else CP_WAIT(0);
        __syncthreads();
        if (c + 2 < 8) load_chunk(c + 2, (c + 2) % 3);
        const uint32_t stg = sb + (uint32_t)(c % 3) * STAGE_BYTES;
        GEMM_COMPUTE2(stg, stg + 16384u);
    }

    #pragma unroll
    for (int i = 0; i < 4; i++)
        #pragma unroll
        for (int half = 0; half < 2; half++) {
            const int rl = m0 + wm*64 + i*16 + (lane >> 2) + half*8;
            #pragma unroll
            for (int j = 0; j < 4; j++) {
                const int cl = n0 + wn*32 + j*8 + (lane & 3)*2;
                const size_t o = (size_t)b*65536 + (size_t)rl*CC_ + cl;
                __nv_bfloat16 h0, l0, h1, l1;
                split_bf16(acc[i][j][half*2+0], h0, l0);
                split_bf16(acc[i][j][half*2+1], h1, l1);
                uint32_t hp = (uint32_t)*(uint16_t*)&h0 | ((uint32_t)*(uint16_t*)&h1 << 16);
                uint32_t lp = (uint32_t)*(uint16_t*)&l0 | ((uint32_t)*(uint16_t*)&l1 << 16);
                *(uint32_t*)(g_weff_hi + o) = hp;
                *(uint32_t*)(g_weff_lo + o) = lp;
            }
        }
}

// ---------------- 11) final GEMM: out = Weff xn + beff + x
__global__ __launch_bounds__(256, 2) void final_gemm_kernel(const float* __restrict__ xres,
                                                            float* __restrict__ out)
{
    extern __shared__ char smem[];
    const uint32_t sb = smem_u32(smem);
    const int tid = threadIdx.x;
    const int lane = tid & 31, wid = tid >> 5;
    const int wm = wid & 1, wn = wid >> 1;
    const int n0 = blockIdx.x * 128, m0 = blockIdx.y * 128, b = blockIdx.z;

    const __nv_bfloat16* Whi = g_weff_hi + (size_t)b * 65536;
    const __nv_bfloat16* Wlo = g_weff_lo + (size_t)b * 65536;

    float acc[4][4][4] = {};
    const int row_a = tid >> 2, u_a = tid & 3;

    auto load_chunk = [&](int chunk, int stage) {
        const int c0 = chunk * 32;
        const uint32_t base = sb + (uint32_t)stage * STAGE_BYTES;
        #pragma unroll
        for (int it = 0; it < 2; it++) {
            const int row = row_a + it*64;
            const uint32_t du = swz_unit(row, u_a);
            const size_t sa = (size_t)(m0 + row)*CC_ + c0 + u_a*8;
            cpasync16(base +         du, Whi + sa);
            cpasync16(base + 8192u + du, Wlo + sa);
            const size_t sx = (size_t)(b*HWN + n0 + row)*CC_ + c0 + u_a*8;
            cpasync16(base + 16384u + du, g_xnT_hi + sx);
            cpasync16(base + 24576u + du, g_xnT_lo + sx);
        }
        CP_COMMIT();
    };

    load_chunk(0, 0);
    load_chunk(1, 1);
    for (int c = 0; c < 8; c++) {
        if (c < 7) CP_WAIT(1); else CP_WAIT(0);
        __syncthreads();
        if (c + 2 < 8) load_chunk(c + 2, (c + 2) % 3);
        const uint32_t stg = sb + (uint32_t)(c % 3) * STAGE_BYTES;
        GEMM_COMPUTE2(stg, stg + 16384u);
    }

    #pragma unroll
    for (int i = 0; i < 4; i++)
        #pragma unroll
        for (int half = 0; half < 2; half++) {
            const int o = m0 + wm*64 + i*16 + (lane >> 2) + half*8;
            const float bv = g_beff[b*CC_ + o];
            const size_t off = ((size_t)(b*CC_ + o))*HWN + n0;
            #pragma unroll
            for (int j = 0; j < 4; j++) {
                const int col = wn*32 + j*8 + (lane & 3)*2;
                float2 xv = *(const float2*)(xres + off + col);
                float2 t;
                t.x = acc[i][j][half*2+0] + bv + xv.x;
                t.y = acc[i][j][half*2+1] + bv + xv.y;
                *(float2*)(out + off + col) = t;
            }
        }
}

// ---------------------------------------------------------------- launch
extern "C" void kernel_launch(void* const* d_in, const int* in_sizes, int n_in,
                              void* d_out, int out_size)
{
    const float* x      = (const float*)d_in[0];
    const float* norm_w = (const float*)d_in[1];
    const float* norm_b = (const float*)d_in[2];
    const float* qkv_w  = (const float*)d_in[3];
    const float* qkv_b  = (const float*)d_in[4];
    const float* proj_w = (const float*)d_in[5];
    const float* proj_b = (const float*)d_in[6];
    float* out = (float*)d_out;

    static bool attr_set = false;
    if (!attr_set) {
        cudaFuncSetAttribute(s_gemm_kernel,
                             cudaFuncAttributeMaxDynamicSharedMemorySize, SMEM_TOTAL_MMA);
        cudaFuncSetAttribute(t_gemm_kernel,
                             cudaFuncAttributeMaxDynamicSharedMemorySize, SMEM_TOTAL_MMA);
        cudaFuncSetAttribute(m_gemm_kernel,
                             cudaFuncAttributeMaxDynamicSharedMemorySize, SMEM_TOTAL_MMA);
        cudaFuncSetAttribute(weff_gemm_kernel,
                             cudaFuncAttributeMaxDynamicSharedMemorySize, SMEM_TOTAL_MMA);
        cudaFuncSetAttribute(final_gemm_kernel,
                             cudaFuncAttributeMaxDynamicSharedMemorySize, SMEM_TOTAL_MMA);
        attr_set = true;
    }

    gn_stats_kernel<<<BB*8, 256>>>(x);
    wprep_kernel<<<768, 256>>>(qkv_w);
    wvt_prep_kernel<<<256, 256>>>(qkv_w);
    gn_apply_t_kernel<<<dim3(128, 8, BB), 256>>>(x, norm_w, norm_b);
    s1_kernel<<<dim3(BB, 32), 256>>>(x, norm_w, norm_b);
    s_gemm_kernel<<<dim3(3, 1, 128), 256, SMEM_TOTAL_MMA>>>();
    s_reduce_kernel<<<dim3(8, 8, BB), 256>>>();
    t_gemm_kernel<<<dim3(2, 2, BB), 256, SMEM_TOTAL_MMA>>>();
    m_gemm_kernel<<<dim3(2, 2, BB), 256, SMEM_TOTAL_MMA>>>();
    uw_kernel<<<dim3(64, BB), 256>>>(qkv_w);
    psoftmax_kernel<<<BB, 256>>>(qkv_b);
    wt_prep_kernel<<<dim3(CC_, BB), 256>>>(proj_w, qkv_b, proj_b);
    weff_gemm_kernel<<<dim3(2, 2, BB), 256, SMEM_TOTAL_MMA>>>();
    final_gemm_kernel<<<dim3(32, 2, BB), 256, SMEM_TOTAL_MMA>>>(x, out);
}

// round 17
// speedup vs baseline: 1.7420x; 1.1560x over previous
#include <cuda_runtime.h>
#include <cuda_bf16.h>
#include <cstdint>

// ---------------------------------------------------------------- constants
#define BB 16
#define CC_ 256
#define HWN 4096
#define EPSV 1e-5f
#define TOTAL (BB*CC_*HWN)   // 16,777,216

// ---------------------------------------------------------------- scratch
__device__ __nv_bfloat16 g_xnT_hi[TOTAL];      // [b][n][c]
__device__ __nv_bfloat16 g_xnT_lo[TOTAL];
__device__ __nv_bfloat16 g_xnC_hi[TOTAL];      // [b][c][n]
__device__ __nv_bfloat16 g_xnC_lo[TOTAL];
__device__ __nv_bfloat16 g_wqkv_hi[768*256];
__device__ __nv_bfloat16 g_wqkv_lo[768*256];
__device__ __nv_bfloat16 g_wvT_hi[256*256];    // WvT[c][c'] = Wv[c'][c]
__device__ __nv_bfloat16 g_wvT_lo[256*256];
__device__ float g_Spart[128*3*16384];         // [z][blk:D0,D1,O][128][128]
__device__ __nv_bfloat16 g_S_hi[BB*256*256];
__device__ __nv_bfloat16 g_S_lo[BB*256*256];
__device__ __nv_bfloat16 g_T_hi[BB*256*256];   // T = Wq * S (bf16 hi/lo)
__device__ __nv_bfloat16 g_T_lo[BB*256*256];
__device__ float g_uw[BB*512];                 // [b][r<256: Wq.s1 | r>=256: Wk.s1]
__device__ float g_s1x[BB*256];                // raw per-channel sums of x
__device__ float g_P[BB*64*16];
__device__ __nv_bfloat16 g_wt_hi[BB*256*256];  // W~ (P-folded proj)
__device__ __nv_bfloat16 g_wt_lo[BB*256*256];
__device__ __nv_bfloat16 g_weff_hi[BB*256*256];
__device__ __nv_bfloat16 g_weff_lo[BB*256*256];
__device__ float g_beff[BB*256];
__device__ float g_mean[BB*8];
__device__ float g_rstd[BB*8];

// ---------------------------------------------------------------- PTX helpers
__device__ __forceinline__ uint32_t smem_u32(const void* p) {
    uint32_t a;
    asm("{ .reg .u64 t; cvta.to.shared.u64 t, %1; cvt.u32.u64 %0, t; }" : "=r"(a) : "l"(p));
    return a;
}
__device__ __forceinline__ void ldsm4(uint32_t* r, uint32_t addr) {
    asm volatile("ldmatrix.sync.aligned.m8n8.x4.shared.b16 {%0,%1,%2,%3}, [%4];"
                 : "=r"(r[0]), "=r"(r[1]), "=r"(r[2]), "=r"(r[3]) : "r"(addr));
}
__device__ __forceinline__ void mma16816(float* d, const uint32_t* a, const uint32_t* b) {
    asm volatile("mma.sync.aligned.m16n8k16.row.col.f32.bf16.bf16.f32 "
                 "{%0,%1,%2,%3}, {%4,%5,%6,%7}, {%8,%9}, {%0,%1,%2,%3};"
                 : "+f"(d[0]), "+f"(d[1]), "+f"(d[2]), "+f"(d[3])
                 : "r"(a[0]), "r"(a[1]), "r"(a[2]), "r"(a[3]), "r"(b[0]), "r"(b[1]));
}
__device__ __forceinline__ void cpasync16(uint32_t dst, const void* src) {
    asm volatile("cp.async.cg.shared.global [%0], [%1], 16;" :: "r"(dst), "l"(src));
}
#define CP_COMMIT() asm volatile("cp.async.commit_group;" ::: "memory")
#define CP_WAIT(n)  asm volatile("cp.async.wait_group %0;" :: "n"(n) : "memory")

__device__ __forceinline__ uint32_t swz_unit(int row, int u) {
    return (uint32_t)((row*4 + (u ^ ((row >> 1) & 3))) * 16);
}
__device__ __forceinline__ void split_bf16(float v, __nv_bfloat16& hi, __nv_bfloat16& lo) {
    hi = __float2bfloat16(v);
    lo = __float2bfloat16(v - __bfloat162float(hi));
}
__device__ __forceinline__ uint32_t pack_hi(float a, float b) {
    __nv_bfloat16 h0 = __float2bfloat16(a), h1 = __float2bfloat16(b);
    return (uint32_t)*(uint16_t*)&h0 | ((uint32_t)*(uint16_t*)&h1 << 16);
}
__device__ __forceinline__ uint32_t pack_lo(float a, float b) {
    __nv_bfloat16 h0 = __float2bfloat16(a), h1 = __float2bfloat16(b);
    __nv_bfloat16 l0 = __float2bfloat16(a - __bfloat162float(h0));
    __nv_bfloat16 l1 = __float2bfloat16(b - __bfloat162float(h1));
    return (uint32_t)*(uint16_t*)&l0 | ((uint32_t)*(uint16_t*)&l1 << 16);
}

#define STAGE_BYTES 32768
#define SMEM_TOTAL_MMA (STAGE_BYTES*3)   // 98304

// GEMM inner machinery with separate A/B smem bases.
#define GEMM_COMPUTE2(ab_expr, bb_expr)                                           \
    {                                                                             \
        const uint32_t ab = (ab_expr);                                            \
        const uint32_t bb = (bb_expr);                                            \
        _Pragma("unroll")                                                         \
        for (int ks = 0; ks < 2; ks++) {                                          \
            uint32_t a0[4][4], a1[4][4], bb0[4][2], bb1[4][2];                    \
            _Pragma("unroll")                                                     \
            for (int i = 0; i < 4; i++) {                                         \
                const int row = wm*64 + i*16 + (lane & 15);                       \
                const int u   = ks*2 + (lane >> 4);                               \
                ldsm4(a0[i], ab + swz_unit(row, u));                              \
            }                                                                     \
            _Pragma("unroll")                                                     \
            for (int jj = 0; jj < 2; jj++) {                                      \
                const int row = wn*32 + jj*16 + ((lane >> 4) & 1)*8 + (lane & 7); \
                const int u   = ks*2 + ((lane >> 3) & 1);                         \
                uint32_t r[4];                                                    \
                ldsm4(r, bb + swz_unit(row, u));                                  \
                bb0[jj*2+0][0] = r[0]; bb0[jj*2+0][1] = r[1];                     \
                bb0[jj*2+1][0] = r[2]; bb0[jj*2+1][1] = r[3];                     \
            }                                                                     \
            _Pragma("unroll")                                                     \
            for (int i = 0; i < 4; i++)                                           \
                _Pragma("unroll")                                                 \
                for (int j = 0; j < 4; j++)                                       \
                    mma16816(acc[i][j], a0[i], bb0[j]);                           \
            _Pragma("unroll")                                                     \
            for (int i = 0; i < 4; i++) {                                         \
                const int row = wm*64 + i*16 + (lane & 15);                       \
                const int u   = ks*2 + (lane >> 4);                               \
                ldsm4(a1[i], ab + 8192u + swz_unit(row, u));                      \
            }                                                                     \
            _Pragma("unroll")                                                     \
            for (int i = 0; i < 4; i++)                                           \
                _Pragma("unroll")                                                 \
                for (int j = 0; j < 4; j++)                                       \
                    mma16816(acc[i][j], a1[i], bb0[j]);                           \
            _Pragma("unroll")                                                     \
            for (int jj = 0; jj < 2; jj++) {                                      \
                const int row = wn*32 + jj*16 + ((lane >> 4) & 1)*8 + (lane & 7); \
                const int u   = ks*2 + ((lane >> 3) & 1);                         \
                uint32_t r[4];                                                    \
                ldsm4(r, bb + 8192u + swz_unit(row, u));                          \
                bb1[jj*2+0][0] = r[0]; bb1[jj*2+0][1] = r[1];                     \
                bb1[jj*2+1][0] = r[2]; bb1[jj*2+1][1] = r[3];                     \
            }                                                                     \
            _Pragma("unroll")                                                     \
            for (int i = 0; i < 4; i++)                                           \
                _Pragma("unroll")                                                 \
                for (int j = 0; j < 4; j++)                                       \
                    mma16816(acc[i][j], a0[i], bb1[j]);                           \
        }                                                                         \
    }

// ---------------- 1) GN stats + per-channel raw sums (8 lanes per channel)
__global__ __launch_bounds__(256) void gn_stats_kernel(const float* __restrict__ x)
{
    const int bg  = blockIdx.x;
    const int tid = threadIdx.x;
    const int ch = tid >> 3, sub = tid & 7;
    const float4* p4 = (const float4*)(x + (size_t)bg * 32 * HWN);

    float s = 0.f, s2 = 0.f;
    #pragma unroll 4
    for (int k = 0; k < 128; k++) {
        float4 v = p4[ch*1024 + sub + k*8];
        s  += v.x + v.y + v.z + v.w;
        s2 += v.x*v.x + v.y*v.y + v.z*v.z + v.w*v.w;
    }
    // channel sum over the 8-lane group
    #pragma unroll
    for (int o = 4; o > 0; o >>= 1) s += __shfl_xor_sync(0xffffffff, s, o);
    __shared__ float chs[32];
    if (sub == 0) { g_s1x[bg*32 + ch] = s; chs[ch] = s; }

    __shared__ float rs2[256];
    rs2[tid] = s2;
    __syncthreads();
    for (int off = 128; off > 0; off >>= 1) {
        if (tid < off) rs2[tid] += rs2[tid+off];
        __syncthreads();
    }
    if (tid == 0) {
        float tot = 0.f;
        #pragma unroll
        for (int i = 0; i < 32; i++) tot += chs[i];
        const float inv_n = 1.f / (float)(32*HWN);
        float mean = tot * inv_n;
        float var  = rs2[0] * inv_n - mean*mean;
        g_mean[bg] = mean;
        g_rstd[bg] = rsqrtf(var + EPSV);
    }
}

// ---------------- 2) GN apply -> xnC hi/lo [c][n] and xnT hi/lo [n][c] (vectorized)
__global__ __launch_bounds__(256) void gn_apply_t_kernel(const float* __restrict__ x,
                                                         const float* __restrict__ nw,
                                                         const float* __restrict__ nb)
{
    const int nt = blockIdx.x, ct = blockIdx.y, b = blockIdx.z;
    const int n0 = nt*64, c0 = ct*64;
    const int tid = threadIdx.x;
    __shared__ float tile[64][65];
    __shared__ float swv[64], sbv[64];

    if (tid < 64) {
        const int c = c0 + tid;
        const float rstd = g_rstd[b*8 + (c >> 5)];
        const float mean = g_mean[b*8 + (c >> 5)];
        const float sw = nw[c]*rstd;
        swv[tid] = sw;
        sbv[tid] = nb[c] - mean*sw;
    }
    __syncthreads();

    #pragma unroll
    for (int p = 0; p < 8; p++) {
        const int g = tid + p*256;          // over 64c x 32 n-pairs
        const int cl = g >> 5, np = g & 31;
        const size_t src = ((size_t)(b*CC_ + c0 + cl))*HWN + n0 + np*2;
        float2 v = *(const float2*)(x + src);
        const float sw = swv[cl], sb = sbv[cl];
        v.x = v.x*sw + sb; v.y = v.y*sw + sb;
        tile[cl][np*2] = v.x; tile[cl][np*2+1] = v.y;
        *(uint32_t*)(g_xnC_hi + src) = pack_hi(v.x, v.y);
        *(uint32_t*)(g_xnC_lo + src) = pack_lo(v.x, v.y);
    }
    __syncthreads();
    #pragma unroll
    for (int p = 0; p < 8; p++) {
        const int g = tid + p*256;          // over 64n x 32 c-pairs
        const int nl = g >> 5, cp = g & 31;
        const float v0 = tile[cp*2][nl], v1 = tile[cp*2+1][nl];
        const size_t dst = ((size_t)(b*HWN + n0 + nl))*CC_ + c0 + cp*2;
        *(uint32_t*)(g_xnT_hi + dst) = pack_hi(v0, v1);
        *(uint32_t*)(g_xnT_lo + dst) = pack_lo(v0, v1);
    }
}

// ---------------------------------------------------------------- 3) weight preps
__global__ __launch_bounds__(256) void wprep_kernel(const float* __restrict__ qkv_w)
{
    const int i = blockIdx.x * 256 + threadIdx.x;
    if (i < 768*256) {
        __nv_bfloat16 hi, lo; split_bf16(qkv_w[i], hi, lo);
        g_wqkv_hi[i] = hi; g_wqkv_lo[i] = lo;
    }
}
__global__ __launch_bounds__(256) void wvt_prep_kernel(const float* __restrict__ qkv_w)
{
    const int c = blockIdx.x, cp = threadIdx.x;
    __nv_bfloat16 hi, lo; split_bf16(qkv_w[(512 + cp)*CC_ + c], hi, lo);
    g_wvT_hi[c*CC_ + cp] = hi; g_wvT_lo[c*CC_ + cp] = lo;
}

// ---------------- 5) S symmetric split-K GEMM (unchanged from R16)
__global__ __launch_bounds__(256, 2) void s_gemm_kernel()
{
    extern __shared__ char smem[];
    const uint32_t sb = smem_u32(smem);
    const int tid = threadIdx.x;
    const int lane = tid & 31, wid = tid >> 5;
    const int wm = wid & 1, wn = wid >> 1;
    const int t = blockIdx.x;
    const int z = blockIdx.z, b = z >> 3, seg = z & 7;
    const int segoff = seg * 512;
    const int m0 = (t == 1) ? 128 : 0;
    const int n0 = (t == 0) ? 0 : 128;
    const bool diag = (t < 2);

    const __nv_bfloat16* Ahi = g_xnC_hi + (size_t)b*CC_*HWN;
    const __nv_bfloat16* Alo = g_xnC_lo + (size_t)b*CC_*HWN;

    float acc[4][4][4] = {};
    const int row_a = tid >> 2, u_a = tid & 3;

    auto load_chunk = [&](int chunk, int stage) {
        const int c0 = segoff + chunk * 32;
        const uint32_t base = sb + (uint32_t)stage * STAGE_BYTES;
        #pragma unroll
        for (int it = 0; it < 2; it++) {
            const int row = row_a + it*64;
            const uint32_t du = swz_unit(row, u_a);
            const size_t sa = (size_t)(m0 + row)*HWN + c0 + u_a*8;
            cpasync16(base +         du, Ahi + sa);
            cpasync16(base + 8192u + du, Alo + sa);
            if (!diag) {
                const size_t sx = (size_t)(n0 + row)*HWN + c0 + u_a*8;
                cpasync16(base + 16384u + du, Ahi + sx);
                cpasync16(base + 24576u + du, Alo + sx);
            }
        }
        CP_COMMIT();
    };

    load_chunk(0, 0);
    load_chunk(1, 1);
    for (int c = 0; c < 16; c++) {
        if (c < 15) CP_WAIT(1); else CP_WAIT(0);
        __syncthreads();
        if (c + 2 < 16) load_chunk(c + 2, (c + 2) % 3);
        const uint32_t stg = sb + (uint32_t)(c % 3) * STAGE_BYTES;
        if (diag) {
            GEMM_COMPUTE2(stg, stg);
        } else {
            GEMM_COMPUTE2(stg, stg + 16384u);
        }
    }

    float* dst = g_Spart + ((size_t)z*3 + t)*16384;
    #pragma unroll
    for (int i = 0; i < 4; i++)
        #pragma unroll
        for (int half = 0; half < 2; half++) {
            const int rl = wm*64 + i*16 + (lane >> 2) + half*8;
            #pragma unroll
            for (int j = 0; j < 4; j++) {
                const int cl = wn*32 + j*8 + (lane & 3)*2;
                float2 v = { acc[i][j][half*2+0], acc[i][j][half*2+1] };
                *(float2*)(dst + rl*128 + cl) = v;
            }
        }
}

// ---------------- 6) reduce S partials (+ transpose reconstruct)
__global__ __launch_bounds__(256) void s_reduce_kernel()
{
    const int tC = blockIdx.x, tR = blockIdx.y, b = blockIdx.z;
    const int col = threadIdx.x & 31, r = threadIdx.x >> 5;
    const bool trans = (tR >= 4 && tC < 4);
    int blk, sR0, sC0;
    if (tR < 4 && tC < 4)        { blk = 0; sR0 = tR*32;       sC0 = tC*32; }
    else if (tR >= 4 && tC >= 4) { blk = 1; sR0 = tR*32 - 128; sC0 = tC*32 - 128; }
    else if (!trans)             { blk = 2; sR0 = tR*32;       sC0 = tC*32 - 128; }
    else                         { blk = 2; sR0 = tC*32;       sC0 = tR*32 - 128; }

    float acc[4] = {};
    if (!trans) {
        #pragma unroll
        for (int seg = 0; seg < 8; seg++) {
            const float* src = g_Spart + ((size_t)(b*8 + seg)*3 + blk)*16384;
            #pragma unroll
            for (int p = 0; p < 4; p++)
                acc[p] += src[(sR0 + r + p*8)*128 + sC0 + col];
        }
    } else {
        __shared__ float sm[32][33];
        #pragma unroll
        for (int seg = 0; seg < 8; seg++) {
            const float* src = g_Spart + ((size_t)(b*8 + seg)*3 + blk)*16384;
            __syncthreads();
            #pragma unroll
            for (int p = 0; p < 4; p++)
                sm[r + p*8][col] = src[(sR0 + r + p*8)*128 + sC0 + col];
            __syncthreads();
            #pragma unroll
            for (int p = 0; p < 4; p++)
                acc[p] += sm[col][r + p*8];
        }
    }
    #pragma unroll
    for (int p = 0; p < 4; p++) {
        const int c1 = tR*32 + r + p*8, c2 = tC*32 + col;
        const size_t idx = (size_t)b*65536 + (size_t)c1*CC_ + c2;
        __nv_bfloat16 hi, lo; split_bf16(acc[p], hi, lo);
        g_S_hi[idx] = hi; g_S_lo[idx] = lo;
    }
}

// ---------------- 7) T = Wq * S -> bf16 hi/lo
__global__ __launch_bounds__(256, 2) void t_gemm_kernel()
{
    extern __shared__ char smem[];
    const uint32_t sb = smem_u32(smem);
    const int tid = threadIdx.x;
    const int lane = tid & 31, wid = tid >> 5;
    const int wm = wid & 1, wn = wid >> 1;
    const int n0 = blockIdx.x * 128, m0 = blockIdx.y * 128, b = blockIdx.z;

    const __nv_bfloat16* Bhi = g_S_hi + (size_t)b*65536;
    const __nv_bfloat16* Blo = g_S_lo + (size_t)b*65536;

    float acc[4][4][4] = {};
    const int row_a = tid >> 2, u_a = tid & 3;

    auto load_chunk = [&](int chunk, int stage) {
        const int c0 = chunk * 32;
        const uint32_t base = sb + (uint32_t)stage * STAGE_BYTES;
        #pragma unroll
        for (int it = 0; it < 2; it++) {
            const int row = row_a + it*64;
            const uint32_t du = swz_unit(row, u_a);
            const size_t sa = (size_t)(m0 + row)*CC_ + c0 + u_a*8;
            cpasync16(base +         du, g_wqkv_hi + sa);
            cpasync16(base + 8192u + du, g_wqkv_lo + sa);
            const size_t sx = (size_t)(n0 + row)*CC_ + c0 + u_a*8;
            cpasync16(base + 16384u + du, Bhi + sx);
            cpasync16(base + 24576u + du, Blo + sx);
        }
        CP_COMMIT();
    };

    load_chunk(0, 0);
    load_chunk(1, 1);
    for (int c = 0; c < 8; c++) {
        if (c < 7) CP_WAIT(1); else CP_WAIT(0);
        __syncthreads();
        if (c + 2 < 8) load_chunk(c + 2, (c + 2) % 3);
        const uint32_t stg = sb + (uint32_t)(c % 3) * STAGE_BYTES;
        GEMM_COMPUTE2(stg, stg + 16384u);
    }

    #pragma unroll
    for (int i = 0; i < 4; i++)
        #pragma unroll
        for (int half = 0; half < 2; half++) {
            const int rl = m0 + wm*64 + i*16 + (lane >> 2) + half*8;
            #pragma unroll
            for (int j = 0; j < 4; j++) {
                const int cl = n0 + wn*32 + j*8 + (lane & 3)*2;
                const size_t o = (size_t)b*65536 + (size_t)rl*CC_ + cl;
                *(uint32_t*)(g_T_hi + o) = pack_hi(acc[i][j][half*2+0], acc[i][j][half*2+1]);
                *(uint32_t*)(g_T_lo + o) = pack_lo(acc[i][j][half*2+0], acc[i][j][half*2+1]);
            }
        }
}

// ---------------- 8a) uw[b][r] = qkv_w[r] . s1[b]  (s1 from raw sums, GN affine inline)
__global__ __launch_bounds__(256) void uw_kernel(const float* __restrict__ qkv_w,
                                                 const float* __restrict__ nw,
                                                 const float* __restrict__ nb)
{
    const int b = blockIdx.y;
    const int rr = blockIdx.x*8 + (threadIdx.x >> 5);
    const int lane = threadIdx.x & 31;
    const float* w = qkv_w + (size_t)rr*CC_;
    float acc = 0.f;
    #pragma unroll
    for (int k = 0; k < 8; k++) {
        const int c = lane + k*32;
        const float rstd = g_rstd[b*8 + (c >> 5)];
        const float mean = g_mean[b*8 + (c >> 5)];
        const float sw = nw[c]*rstd;
        const float s1 = sw*g_s1x[b*CC_ + c] + 4096.f*(nb[c] - mean*sw);
        acc += w[c] * s1;
    }
    #pragma unroll
    for (int o = 16; o > 0; o >>= 1) acc += __shfl_xor_sync(0xffffffff, acc, o);
    if (lane == 0) g_uw[b*512 + rr] = acc;
}

// ---------------- 8b) G dots (T . Wk rows, only needed entries) + softmax -> P
__global__ __launch_bounds__(256) void gp_kernel(const float* __restrict__ qkv_w,
                                                 const float* __restrict__ qkv_b)
{
    const int b = blockIdx.y;
    const int r = blockIdx.x*8 + (threadIdx.x >> 5);    // 0..255
    const int lane = threadIdx.x & 31;
    const int e = r & 63, i = r >> 6;

    const __nv_bfloat16* Th = g_T_hi + (size_t)b*65536 + (size_t)r*CC_;
    const __nv_bfloat16* Tl = g_T_lo + (size_t)b*65536 + (size_t)r*CC_;

    float G[4] = {};
    #pragma unroll
    for (int k = 0; k < 8; k++) {
        const int c = lane + k*32;
        const float tc = __bfloat162float(Th[c]) + __bfloat162float(Tl[c]);
        #pragma unroll
        for (int j = 0; j < 4; j++)
            G[j] += tc * qkv_w[(size_t)(256 + j*64 + e)*CC_ + c];
    }
    #pragma unroll
    for (int j = 0; j < 4; j++)
        #pragma unroll
        for (int o = 16; o > 0; o >>= 1)
            G[j] += __shfl_xor_sync(0xffffffff, G[j], o);

    if (lane == 0) {
        const float bq = qkv_b[r];
        const float uu = g_uw[b*512 + r];
        #pragma unroll
        for (int j = 0; j < 4; j++) {
            const int r2 = j*64 + e;
            G[j] = 0.125f * (G[j] + bq*g_uw[b*512 + 256 + r2]
                             + qkv_b[256 + r2]*uu + 4096.f*bq*qkv_b[256 + r2]);
        }
        float m = fmaxf(fmaxf(G[0], G[1]), fmaxf(G[2], G[3]));
        float e0 = expf(G[0]-m), e1 = expf(G[1]-m), e2 = expf(G[2]-m), e3 = expf(G[3]-m);
        float inv = 1.f / (e0+e1+e2+e3);
        float* P = g_P + ((size_t)(b*64 + e))*16 + i*4;
        P[0] = e0*inv; P[1] = e1*inv; P[2] = e2*inv; P[3] = e3*inv;
    }
}

// ---------------- 9) W~ = fold proj_w with P (hi/lo) + fused beff reduction
__global__ __launch_bounds__(256) void wt_prep_kernel(const float* __restrict__ proj_w,
                                                      const float* __restrict__ qkv_b,
                                                      const float* __restrict__ proj_b)
{
    const int o = blockIdx.x, b = blockIdx.y;
    const int c = threadIdx.x;
    const int e = c & 63, j = c >> 6;
    const float* P = g_P + ((size_t)(b*64 + e))*16 + j;
    float s = 0.f;
    #pragma unroll
    for (int i = 0; i < 4; i++)
        s += proj_w[o*CC_ + i*64 + e] * P[i*4];
    __nv_bfloat16 hi, lo; split_bf16(s, hi, lo);
    const size_t idx = ((size_t)b*CC_ + o)*CC_ + c;
    g_wt_hi[idx] = hi; g_wt_lo[idx] = lo;

    __shared__ float red[256];
    red[c] = s * qkv_b[512 + c];
    __syncthreads();
    for (int off = 128; off > 0; off >>= 1) {
        if (c < off) red[c] += red[c + off];
        __syncthreads();
    }
    if (c == 0) g_beff[b*CC_ + o] = red[0] + proj_b[o];
}

// ---------------- 10) Weff = W~ * WvT
__global__ __launch_bounds__(256, 2) void weff_gemm_kernel()
{
    extern __shared__ char smem[];
    const uint32_t sb = smem_u32(smem);
    const int tid = threadIdx.x;
    const int lane = tid & 31, wid = tid >> 5;
    const int wm = wid & 1, wn = wid >> 1;
    const int n0 = blockIdx.x * 128, m0 = blockIdx.y * 128, b = blockIdx.z;

    const __nv_bfloat16* Ahi = g_wt_hi + (size_t)b*65536;
    const __nv_bfloat16* Alo = g_wt_lo + (size_t)b*65536;

    float acc[4][4][4] = {};
    const int row_a = tid >> 2, u_a = tid & 3;

    auto load_chunk = [&](int chunk, int stage) {
        const int c0 = chunk * 32;
        const uint32_t base = sb + (uint32_t)stage * STAGE_BYTES;
        #pragma unroll
        for (int it = 0; it < 2; it++) {
            const int row = row_a + it*64;
            const uint32_t du = swz_unit(row, u_a);
            const size_t sa = (size_t)(m0 + row)*CC_ + c0 + u_a*8;
            cpasync16(base +         du, Ahi + sa);
            cpasync16(base + 8192u + du, Alo + sa);
            const size_t sx = (size_t)(n0 + row)*CC_ + c0 + u_a*8;
            cpasync16(base + 16384u + du, g_wvT_hi + sx);
            cpasync16(base + 24576u + du, g_wvT_lo + sx);
        }
        CP_COMMIT();
    };

    load_chunk(0, 0);
    load_chunk(1, 1);
    for (int c = 0; c < 8; c++) {
        if (c < 7) CP_WAIT(1); else CP_WAIT(0);
        __syncthreads();
        if (c + 2 < 8) load_chunk(c + 2, (c + 2) % 3);
        const uint32_t stg = sb + (uint32_t)(c % 3) * STAGE_BYTES;
        GEMM_COMPUTE2(stg, stg + 16384u);
    }

    #pragma unroll
    for (int i = 0; i < 4; i++)
        #pragma unroll
        for (int half = 0; half < 2; half++) {
            const int rl = m0 + wm*64 + i*16 + (lane >> 2) + half*8;
            #pragma unroll
            for (int j = 0; j < 4; j++) {
                const int cl = n0 + wn*32 + j*8 + (lane & 3)*2;
                const size_t o = (size_t)b*65536 + (size_t)rl*CC_ + cl;
                *(uint32_t*)(g_weff_hi + o) = pack_hi(acc[i][j][half*2+0], acc[i][j][half*2+1]);
                *(uint32_t*)(g_weff_lo + o) = pack_lo(acc[i][j][half*2+0], acc[i][j][half*2+1]);
            }
        }
}

// ---------------- 11) final GEMM: out = Weff xn + beff + x
__global__ __launch_bounds__(256, 2) void final_gemm_kernel(const float* __restrict__ xres,
                                                            float* __restrict__ out)
{
    extern __shared__ char smem[];
    const uint32_t sb = smem_u32(smem);
    const int tid = threadIdx.x;
    const int lane = tid & 31, wid = tid >> 5;
    const int wm = wid & 1, wn = wid >> 1;
    const int n0 = blockIdx.x * 128, m0 = blockIdx.y * 128, b = blockIdx.z;

    const __nv_bfloat16* Whi = g_weff_hi + (size_t)b * 65536;
    const __nv_bfloat16* Wlo = g_weff_lo + (size_t)b * 65536;

    float acc[4][4][4] = {};
    const int row_a = tid >> 2, u_a = tid & 3;

    auto load_chunk = [&](int chunk, int stage) {
        const int c0 = chunk * 32;
        const uint32_t base = sb + (uint32_t)stage * STAGE_BYTES;
        #pragma unroll
        for (int it = 0; it < 2; it++) {
            const int row = row_a + it*64;
            const uint32_t du = swz_unit(row, u_a);
            const size_t sa = (size_t)(m0 + row)*CC_ + c0 + u_a*8;
            cpasync16(base +         du, Whi + sa);
            cpasync16(base + 8192u + du, Wlo + sa);
            const size_t sx = (size_t)(b*HWN + n0 + row)*CC_ + c0 + u_a*8;
            cpasync16(base + 16384u + du, g_xnT_hi + sx);
            cpasync16(base + 24576u + du, g_xnT_lo + sx);
        }
        CP_COMMIT();
    };

    load_chunk(0, 0);
    load_chunk(1, 1);
    for (int c = 0; c < 8; c++) {
        if (c < 7) CP_WAIT(1); else CP_WAIT(0);
        __syncthreads();
        if (c + 2 < 8) load_chunk(c + 2, (c + 2) % 3);
        const uint32_t stg = sb + (uint32_t)(c % 3) * STAGE_BYTES;
        GEMM_COMPUTE2(stg, stg + 16384u);
    }

    #pragma unroll
    for (int i = 0; i < 4; i++)
        #pragma unroll
        for (int half = 0; half < 2; half++) {
            const int o = m0 + wm*64 + i*16 + (lane >> 2) + half*8;
            const float bv = g_beff[b*CC_ + o];
            const size_t off = ((size_t)(b*CC_ + o))*HWN + n0;
            #pragma unroll
            for (int j = 0; j < 4; j++) {
                const int col = wn*32 + j*8 + (lane & 3)*2;
                float2 xv = *(const float2*)(xres + off + col);
                float2 t;
                t.x = acc[i][j][half*2+0] + bv + xv.x;
                t.y = acc[i][j][half*2+1] + bv + xv.y;
                *(float2*)(out + off + col) = t;
            }
        }
}

// ---------------------------------------------------------------- launch
extern "C" void kernel_launch(void* const* d_in, const int* in_sizes, int n_in,
                              void* d_out, int out_size)
{
    const float* x      = (const float*)d_in[0];
    const float* norm_w = (const float*)d_in[1];
    const float* norm_b = (const float*)d_in[2];
    const float* qkv_w  = (const float*)d_in[3];
    const float* qkv_b  = (const float*)d_in[4];
    const float* proj_w = (const float*)d_in[5];
    const float* proj_b = (const float*)d_in[6];
    float* out = (float*)d_out;

    static bool attr_set = false;
    if (!attr_set) {
        cudaFuncSetAttribute(s_gemm_kernel,
                             cudaFuncAttributeMaxDynamicSharedMemorySize, SMEM_TOTAL_MMA);
        cudaFuncSetAttribute(t_gemm_kernel,
                             cudaFuncAttributeMaxDynamicSharedMemorySize, SMEM_TOTAL_MMA);
        cudaFuncSetAttribute(weff_gemm_kernel,
                             cudaFuncAttributeMaxDynamicSharedMemorySize, SMEM_TOTAL_MMA);
        cudaFuncSetAttribute(final_gemm_kernel,
                             cudaFuncAttributeMaxDynamicSharedMemorySize, SMEM_TOTAL_MMA);
        attr_set = true;
    }

    gn_stats_kernel<<<BB*8, 256>>>(x);
    wprep_kernel<<<768, 256>>>(qkv_w);
    wvt_prep_kernel<<<256, 256>>>(qkv_w);
    gn_apply_t_kernel<<<dim3(64, 4, BB), 256>>>(x, norm_w, norm_b);
    s_gemm_kernel<<<dim3(3, 1, 128), 256, SMEM_TOTAL_MMA>>>();
    s_reduce_kernel<<<dim3(8, 8, BB), 256>>>();
    t_gemm_kernel<<<dim3(2, 2, BB), 256, SMEM_TOTAL_MMA>>>();
    uw_kernel<<<dim3(64, BB), 256>>>(qkv_w, norm_w, norm_b);
    gp_kernel<<<dim3(32, BB), 256>>>(qkv_w, qkv_b);
    wt_prep_kernel<<<dim3(CC_, BB), 256>>>(proj_w, qkv_b, proj_b);
    weff_gemm_kernel<<<dim3(2, 2, BB), 256, SMEM_TOTAL_MMA>>>();
    final_gemm_kernel<<<dim3(32, 2, BB), 256, SMEM_TOTAL_MMA>>>(x, out);
}